// round 4
// baseline (speedup 1.0000x reference)
#include <cuda_runtime.h>
#include <cuda_bf16.h>

// x: [B=16, C=64, H=256, W=256] fp32; conv_w [1,2,7,7]; conv_b [1]
// out = x * sigmoid(conv7x7(concat(mean_c(x), max_c(x))) + b)
//
// Single persistent kernel (all blocks resident), software-pipelined over
// batches with flag gates instead of launch boundaries:
//   phase p: reduce(p) || conv(p-1) || mul(p-2)
// x[b] is read from DRAM once (reduce), re-read by mul from L2.

#define B 16
#define C 64
#define HW 65536           // 256*256
#define HWf4 16384         // HW/4
#define PLANE (C * HW)     // 2^22 elements (16 MB)

#define TW 32
#define TH 8

#define RED_UNITS  512     // per batch: 32 f4-pixels each
#define CONV_UNITS 256     // per batch: one 32x8 tile each
#define MUL_UNITS  4096    // per batch: 256 f4 each
#define PHASE_UNITS (RED_UNITS + CONV_UNITS + MUL_UNITS)   // 4864
#define NPHASE (B + 2)     // 18

#define NB 1184            // 148 SMs x 8 blocks, all resident

__device__ float g_att[B * 2 * HW];
__device__ float g_s[B * HW];
__device__ int red_done[B];
__device__ int conv_done[B];

__device__ __forceinline__ void f4add(float4& a, const float4 b) {
    a.x += b.x; a.y += b.y; a.z += b.z; a.w += b.w;
}
__device__ __forceinline__ void f4max(float4& a, const float4 b) {
    a.x = fmaxf(a.x, b.x); a.y = fmaxf(a.y, b.y);
    a.z = fmaxf(a.z, b.z); a.w = fmaxf(a.w, b.w);
}

__device__ __forceinline__ void wait_ge(volatile int* ctr, int target) {
    if (*ctr < target) {
        while (*ctr < target) __nanosleep(64);
    }
    __threadfence();   // acquire: order subsequent data loads after observation
}

__global__ void k_reset() {
    if (threadIdx.x < B) {
        red_done[threadIdx.x] = 0;
        conv_done[threadIdx.x] = 0;
    }
}

__global__ void __launch_bounds__(256, 8)
k_main(const float* __restrict__ x,
       const float* __restrict__ cw,
       const float* __restrict__ cb,
       float* __restrict__ out) {
    __shared__ __align__(16) char sbuf[8704];

    const int blk = blockIdx.x;
    const int tid = threadIdx.x;

    for (int p = 0; p < NPHASE; p++) {
        for (int u = blk; u < PHASE_UNITS; u += NB) {
            if (u < RED_UNITS) {
                // ---- reduce(batch p): mean+max over C for 32 f4-pixels ----
                int b = p;
                if (b >= B) continue;
                int px = tid & 31;
                int g  = tid >> 5;
                int q4 = u * 32 + px;

                const float4* xb = reinterpret_cast<const float4*>(x + (size_t)b * PLANE);
                int c0 = g * 8;
                float4 sum = xb[(size_t)c0 * HWf4 + q4];
                float4 mx  = sum;
#pragma unroll
                for (int c = 1; c < 8; c++) {
                    float4 v = xb[(size_t)(c0 + c) * HWf4 + q4];
                    f4add(sum, v);
                    f4max(mx, v);
                }

                float4* ssum = reinterpret_cast<float4*>(sbuf);   // [8][32]
                float4* smax = ssum + 256;
                ssum[g * 32 + px] = sum;
                smax[g * 32 + px] = mx;
                __syncthreads();

                if (g == 0) {
                    float4 s = ssum[px];
                    float4 m = smax[px];
#pragma unroll
                    for (int gg = 1; gg < 8; gg++) {
                        f4add(s, ssum[gg * 32 + px]);
                        f4max(m, smax[gg * 32 + px]);
                    }
                    const float inv = 1.0f / 64.0f;
                    float4* avg_out = reinterpret_cast<float4*>(g_att + (size_t)b * 2 * HW);
                    float4* max_out = reinterpret_cast<float4*>(g_att + (size_t)b * 2 * HW + HW);
                    avg_out[q4] = make_float4(s.x * inv, s.y * inv, s.z * inv, s.w * inv);
                    max_out[q4] = m;
                }
                __syncthreads();
                if (tid == 0) {
                    __threadfence();
                    atomicAdd(&red_done[b], 1);
                }

            } else if (u < RED_UNITS + CONV_UNITS) {
                // ---- conv(batch p-1): 7x7 + bias + sigmoid on one tile ----
                int b = p - 1;
                if (b < 0 || b >= B) continue;
                wait_ge(red_done + b, RED_UNITS);

                int idx = u - RED_UNITS;
                int w0 = (idx & 7) * TW;
                int h0 = (idx >> 3) * TH;

                float* s_avg = reinterpret_cast<float*>(sbuf);    // [14][40]
                float* s_mx  = s_avg + 14 * 40;
                float* s_w   = s_mx + 14 * 40;                    // [98]
                float* s_b   = s_w + 98;

                if (tid < 98) s_w[tid] = cw[tid];
                if (tid == 0) s_b[0] = cb[0];

                const float* avgp = g_att + (size_t)b * 2 * HW;
                const float* maxp = avgp + HW;

                for (int i = tid; i < 14 * 38; i += 256) {
                    int dy = i / 38, dx = i - dy * 38;
                    int hh = h0 - 3 + dy, ww = w0 - 3 + dx;
                    float a = 0.f, m = 0.f;
                    if (hh >= 0 && hh < 256 && ww >= 0 && ww < 256) {
                        int ii = hh * 256 + ww;
                        a = avgp[ii];
                        m = maxp[ii];
                    }
                    s_avg[dy * 40 + dx] = a;
                    s_mx[dy * 40 + dx]  = m;
                }
                __syncthreads();

                int lx = tid & (TW - 1);
                int ly = tid >> 5;
                float acc = s_b[0];
#pragma unroll
                for (int kh = 0; kh < 7; kh++) {
#pragma unroll
                    for (int kw = 0; kw < 7; kw++) {
                        acc = fmaf(s_w[kh * 7 + kw],      s_avg[(ly + kh) * 40 + lx + kw], acc);
                        acc = fmaf(s_w[49 + kh * 7 + kw], s_mx[(ly + kh) * 40 + lx + kw], acc);
                    }
                }
                float sg = 1.0f / (1.0f + __expf(-acc));
                g_s[(size_t)b * HW + (h0 + ly) * 256 + (w0 + lx)] = sg;
                __syncthreads();
                if (tid == 0) {
                    __threadfence();
                    atomicAdd(&conv_done[b], 1);
                }

            } else {
                // ---- mul(batch p-2): out = x * s for 256 f4 ----
                int b = p - 2;
                if (b < 0 || b >= B) continue;
                wait_ge(conv_done + b, CONV_UNITS);

                int idx = u - (RED_UNITS + CONV_UNITS);
                int t = idx * 256 + tid;
                int q4 = t & (HWf4 - 1);

                const float4* xb = reinterpret_cast<const float4*>(x + (size_t)b * PLANE);
                float4* ob = reinterpret_cast<float4*>(out + (size_t)b * PLANE);
                const float4* sb = reinterpret_cast<const float4*>(g_s + (size_t)b * HW);

                float4 xv = __ldcs(xb + t);
                float4 sv = sb[q4];
                xv.x *= sv.x; xv.y *= sv.y; xv.z *= sv.z; xv.w *= sv.w;
                __stcs(ob + t, xv);
            }
        }
    }
}

extern "C" void kernel_launch(void* const* d_in, const int* in_sizes, int n_in,
                              void* d_out, int out_size) {
    const float* x  = (const float*)d_in[0];
    const float* cw = (const float*)d_in[1];
    const float* cb = (const float*)d_in[2];
    float* out = (float*)d_out;

    k_reset<<<1, 32>>>();
    k_main<<<NB, 256>>>(x, cw, cb, out);
}

// round 5
// speedup vs baseline: 2.6738x; 2.6738x over previous
#include <cuda_runtime.h>
#include <cuda_bf16.h>

// x: [B=16, C=64, H=256, W=256] fp32; conv_w [1,2,7,7]; conv_b [1]
// out = x * sigmoid(conv7x7(concat(mean_c(x), max_c(x))) + b)
//
// Persistent pipelined kernel, fixed block roles, 18 phases:
//   phase p: reduce(p) || conv(p-1) || mul(p-2)
// x[b] read from DRAM once by reduce; mul re-reads it from L2.
// Gates: one thread spins on a flag, then block-wide __syncthreads.

#define B 16
#define C 64
#define HW 65536
#define HWf4 16384
#define PLANE (C * HW)

#define TW 32
#define TH 8

#define RED_UNITS  512     // per batch, 32 f4-pixels each
#define CONV_UNITS 256     // per batch, one 32x8 tile each
#define MUL_UNITS  4096    // per batch, 256 f4 each
#define NPHASE (B + 2)

#define NB 1184            // 148 SMs x 8 resident blocks

__device__ float g_att[B * 2 * HW];
__device__ float g_s[B * HW];
__device__ int red_done[B];
__device__ int conv_done[B];

__device__ __forceinline__ void f4add(float4& a, const float4 b) {
    a.x += b.x; a.y += b.y; a.z += b.z; a.w += b.w;
}
__device__ __forceinline__ void f4max(float4& a, const float4 b) {
    a.x = fmaxf(a.x, b.x); a.y = fmaxf(a.y, b.y);
    a.z = fmaxf(a.z, b.z); a.w = fmaxf(a.w, b.w);
}

// One thread polls, whole block releases via barrier.
__device__ __forceinline__ void gate(int* ctr, int target) {
    if (threadIdx.x == 0) {
        volatile int* v = (volatile int*)ctr;
        while (*v < target) __nanosleep(64);
    }
    __syncthreads();
}

__global__ void k_reset() {
    if (threadIdx.x < B) {
        red_done[threadIdx.x] = 0;
        conv_done[threadIdx.x] = 0;
    }
}

__global__ void __launch_bounds__(256, 8)
k_main(const float* __restrict__ x,
       const float* __restrict__ cw,
       const float* __restrict__ cb,
       float* __restrict__ out) {
    __shared__ __align__(16) char sbuf[8704];

    const int blk = blockIdx.x;
    const int tid = threadIdx.x;

    // ---- fixed mul-unit assignment (byte-balanced across roles) ----
    // blocks 0..511   : 2 mul units  (1024)
    // blocks 512..895 : 5 mul units  (1920)   [512..767 also do conv]
    // blocks 896..1183: 4 mul units  (1152)   total 4096
    int nm, m0;
    if (blk < 512)      { nm = 2; m0 = blk * 2; }
    else if (blk < 896) { nm = 5; m0 = 1024 + (blk - 512) * 5; }
    else                { nm = 4; m0 = 2944 + (blk - 896) * 4; }

    for (int p = 0; p < NPHASE; p++) {
        // ================= reduce(batch p) =================
        if (blk < RED_UNITS && p < B) {
            const int b = p;
            const int px = tid & 31;
            const int g  = tid >> 5;
            const int q4 = blk * 32 + px;

            const float4* xb = reinterpret_cast<const float4*>(x + (size_t)b * PLANE);
            const int c0 = g * 8;
            float4 sum = xb[(size_t)c0 * HWf4 + q4];
            float4 mx  = sum;
#pragma unroll
            for (int c = 1; c < 8; c++) {
                float4 v = xb[(size_t)(c0 + c) * HWf4 + q4];
                f4add(sum, v);
                f4max(mx, v);
            }

            float4* ssum = reinterpret_cast<float4*>(sbuf);   // [8][32]
            float4* smax = ssum + 256;
            ssum[g * 32 + px] = sum;
            smax[g * 32 + px] = mx;
            __syncthreads();

            if (g == 0) {
                float4 s = ssum[px];
                float4 m = smax[px];
#pragma unroll
                for (int gg = 1; gg < 8; gg++) {
                    f4add(s, ssum[gg * 32 + px]);
                    f4max(m, smax[gg * 32 + px]);
                }
                const float inv = 1.0f / 64.0f;
                float4* avg_out = reinterpret_cast<float4*>(g_att + (size_t)b * 2 * HW);
                float4* max_out = reinterpret_cast<float4*>(g_att + (size_t)b * 2 * HW + HW);
                avg_out[q4] = make_float4(s.x * inv, s.y * inv, s.z * inv, s.w * inv);
                max_out[q4] = m;
            }
            __syncthreads();
            if (tid == 0) {
                __threadfence();
                atomicAdd(&red_done[b], 1);
            }
        }

        // ================= conv(batch p-1) =================
        if (blk >= 512 && blk < 512 + CONV_UNITS && p >= 1 && p <= B) {
            const int b = p - 1;
            gate(red_done + b, RED_UNITS);

            const int idx = blk - 512;
            const int w0 = (idx & 7) * TW;
            const int h0 = (idx >> 3) * TH;

            float* s_avg = reinterpret_cast<float*>(sbuf);    // [14][40]
            float* s_mx  = s_avg + 14 * 40;
            float* s_w   = s_mx + 14 * 40;                    // [98]
            float* s_b   = s_w + 98;

            if (tid < 98) s_w[tid] = cw[tid];
            if (tid == 0) s_b[0] = cb[0];

            const float* avgp = g_att + (size_t)b * 2 * HW;
            const float* maxp = avgp + HW;

            for (int i = tid; i < 14 * 38; i += 256) {
                int dy = i / 38, dx = i - dy * 38;
                int hh = h0 - 3 + dy, ww = w0 - 3 + dx;
                float a = 0.f, m = 0.f;
                if (hh >= 0 && hh < 256 && ww >= 0 && ww < 256) {
                    int ii = hh * 256 + ww;
                    a = __ldcg(avgp + ii);
                    m = __ldcg(maxp + ii);
                }
                s_avg[dy * 40 + dx] = a;
                s_mx[dy * 40 + dx]  = m;
            }
            __syncthreads();

            const int lx = tid & (TW - 1);
            const int ly = tid >> 5;
            float acc = s_b[0];
#pragma unroll
            for (int kh = 0; kh < 7; kh++) {
#pragma unroll
                for (int kw = 0; kw < 7; kw++) {
                    acc = fmaf(s_w[kh * 7 + kw],      s_avg[(ly + kh) * 40 + lx + kw], acc);
                    acc = fmaf(s_w[49 + kh * 7 + kw], s_mx[(ly + kh) * 40 + lx + kw], acc);
                }
            }
            float sg = 1.0f / (1.0f + __expf(-acc));
            g_s[(size_t)b * HW + (h0 + ly) * 256 + (w0 + lx)] = sg;
            __syncthreads();
            if (tid == 0) {
                __threadfence();
                atomicAdd(&conv_done[b], 1);
            }
        }

        // ================= mul(batch p-2) =================
        if (p >= 2) {
            const int b = p - 2;
            gate(conv_done + b, CONV_UNITS);

            const float4* xb = reinterpret_cast<const float4*>(x + (size_t)b * PLANE);
            float4* ob = reinterpret_cast<float4*>(out + (size_t)b * PLANE);
            const float* sb = g_s + (size_t)b * HW;

#pragma unroll
            for (int mu = 0; mu < 5; mu++) {
                if (mu >= nm) break;
                const int t = (m0 + mu) * 256 + tid;
                const int q4 = t & (HWf4 - 1);

                float4 xv = __ldcs(xb + t);
                float4 sv;
                sv.x = __ldcg(sb + q4 * 4 + 0);
                sv.y = __ldcg(sb + q4 * 4 + 1);
                sv.z = __ldcg(sb + q4 * 4 + 2);
                sv.w = __ldcg(sb + q4 * 4 + 3);
                xv.x *= sv.x; xv.y *= sv.y; xv.z *= sv.z; xv.w *= sv.w;
                __stcs(ob + t, xv);
            }
        }
    }
}

extern "C" void kernel_launch(void* const* d_in, const int* in_sizes, int n_in,
                              void* d_out, int out_size) {
    const float* x  = (const float*)d_in[0];
    const float* cw = (const float*)d_in[1];
    const float* cb = (const float*)d_in[2];
    float* out = (float*)d_out;

    k_reset<<<1, 32>>>();
    k_main<<<NB, 256>>>(x, cw, cb, out);
}

// round 6
// speedup vs baseline: 2.8772x; 1.0761x over previous
#include <cuda_runtime.h>
#include <cuda_bf16.h>

// x: [B=16, C=64, H=256, W=256] fp32; conv_w [1,2,7,7]; conv_b [1]
// out = x * sigmoid(conv7x7(concat(mean_c(x), max_c(x))) + b)
//
// Persistent pipelined kernel, 18 phases: phase p runs
//   reduce(p) || conv(p-1) || mul(p-2)
// x[b] read from DRAM once; mul re-reads it from L2 (~1 phase old).
// Roles byte-balanced so no block straggles a phase.

#define B 16
#define C 64
#define HW 65536
#define HWf4 16384
#define PLANE (C * HW)

#define RED_UNITS  512     // 32 f4-pixels each
#define CONV_UNITS 64      // 64x16 tile each
#define MUL_UNITS  4096    // 256 f4 each
#define NPHASE (B + 2)

#define NB 1184            // 148 SMs x 8 resident blocks

__device__ float g_att[B * 2 * HW];
__device__ float g_s[B * HW];
__device__ int red_done[B];
__device__ int conv_done[B];

__device__ __forceinline__ void f4add(float4& a, const float4 b) {
    a.x += b.x; a.y += b.y; a.z += b.z; a.w += b.w;
}
__device__ __forceinline__ void f4max(float4& a, const float4 b) {
    a.x = fmaxf(a.x, b.x); a.y = fmaxf(a.y, b.y);
    a.z = fmaxf(a.z, b.z); a.w = fmaxf(a.w, b.w);
}

__device__ __forceinline__ void gate(int* ctr, int target) {
    if (threadIdx.x == 0) {
        volatile int* v = (volatile int*)ctr;
        while (*v < target) __nanosleep(64);
    }
    __syncthreads();
}

__global__ void k_reset() {
    if (threadIdx.x < B) {
        red_done[threadIdx.x] = 0;
        conv_done[threadIdx.x] = 0;
    }
}

__global__ void __launch_bounds__(256, 8)
k_main(const float* __restrict__ x,
       const float* __restrict__ cw,
       const float* __restrict__ cb,
       float* __restrict__ out) {
    __shared__ __align__(16) char sbuf[13072];

    const int blk = blockIdx.x;
    const int tid = threadIdx.x;

    // ---- byte-balanced mul-unit assignment ----
    // blk 0..511   (reduce): 1 mul unit   -> units 0..511
    // blk 512..575 (conv):   4 mul units  -> units 512..767
    // blk 576..863:          6 mul units  -> units 768..2495
    // blk 864..1183:         5 mul units  -> units 2496..4095
    int nm, m0;
    if (blk < 512)      { nm = 1; m0 = blk; }
    else if (blk < 576) { nm = 4; m0 = 512 + (blk - 512) * 4; }
    else if (blk < 864) { nm = 6; m0 = 768 + (blk - 576) * 6; }
    else                { nm = 5; m0 = 2496 + (blk - 864) * 5; }

    for (int p = 0; p < NPHASE; p++) {
        // ================= reduce(batch p) =================
        if (blk < RED_UNITS && p < B) {
            const int b = p;
            const int px = tid & 31;
            const int g  = tid >> 5;
            const int q4 = blk * 32 + px;

            const float4* xb = reinterpret_cast<const float4*>(x + (size_t)b * PLANE);
            const int c0 = g * 8;
            float4 sum = xb[(size_t)c0 * HWf4 + q4];
            float4 mx  = sum;
#pragma unroll
            for (int c = 1; c < 8; c++) {
                float4 v = xb[(size_t)(c0 + c) * HWf4 + q4];
                f4add(sum, v);
                f4max(mx, v);
            }

            float4* ssum = reinterpret_cast<float4*>(sbuf);   // [8][32]
            float4* smax = ssum + 256;
            ssum[g * 32 + px] = sum;
            smax[g * 32 + px] = mx;
            __syncthreads();

            if (g == 0) {
                float4 s = ssum[px];
                float4 m = smax[px];
#pragma unroll
                for (int gg = 1; gg < 8; gg++) {
                    f4add(s, ssum[gg * 32 + px]);
                    f4max(m, smax[gg * 32 + px]);
                }
                const float inv = 1.0f / 64.0f;
                float4* avg_out = reinterpret_cast<float4*>(g_att + (size_t)b * 2 * HW);
                float4* max_out = reinterpret_cast<float4*>(g_att + (size_t)b * 2 * HW + HW);
                avg_out[q4] = make_float4(s.x * inv, s.y * inv, s.z * inv, s.w * inv);
                max_out[q4] = m;
            }
            __syncthreads();
            if (tid == 0) {
                __threadfence();
                atomicAdd(&red_done[b], 1);
            }
            __syncthreads();   // protect sbuf before any later reuse
        }

        // ================= conv(batch p-1), 64x16 tiles =================
        if (blk >= 512 && blk < 512 + CONV_UNITS && p >= 1 && p <= B) {
            const int b = p - 1;
            gate(red_done + b, RED_UNITS);

            const int idx = blk - 512;              // [0,64)
            const int w0 = (idx & 3) * 64;          // 4 tiles in w
            const int h0 = (idx >> 2) * 16;         // 16 tiles in h

            float* s_avg = reinterpret_cast<float*>(sbuf);      // [22][72]
            float* s_mx  = s_avg + 22 * 72;                     // [22][72]
            float* s_w   = s_mx + 22 * 72;                      // [98]
            float* s_b   = s_w + 98;

            if (tid < 98) s_w[tid] = cw[tid];
            if (tid == 98) s_b[0] = cb[0];

            const float* avgp = g_att + (size_t)b * 2 * HW;
            const float* maxp = avgp + HW;

            for (int i = tid; i < 22 * 70; i += 256) {
                int dy = i / 70, dx = i - dy * 70;
                int hh = h0 - 3 + dy, ww = w0 - 3 + dx;
                float a = 0.f, m = 0.f;
                if (hh >= 0 && hh < 256 && ww >= 0 && ww < 256) {
                    int ii = hh * 256 + ww;
                    a = __ldcg(avgp + ii);
                    m = __ldcg(maxp + ii);
                }
                s_avg[dy * 72 + dx] = a;
                s_mx[dy * 72 + dx]  = m;
            }
            __syncthreads();

            const int tx = tid & 15;          // 16 groups of 4 outputs in w
            const int ty = tid >> 4;          // 16 rows
            const int ow0 = tx * 4;

            float a0 = s_b[0], a1 = a0, a2 = a0, a3 = a0;
#pragma unroll
            for (int kh = 0; kh < 7; kh++) {
                const float* ra = s_avg + (ty + kh) * 72 + ow0;
                const float* rm = s_mx  + (ty + kh) * 72 + ow0;
                float v[10];
#pragma unroll
                for (int j = 0; j < 10; j++) v[j] = ra[j];
#pragma unroll
                for (int kw = 0; kw < 7; kw++) {
                    float wA = s_w[kh * 7 + kw];
                    a0 = fmaf(wA, v[kw],     a0);
                    a1 = fmaf(wA, v[kw + 1], a1);
                    a2 = fmaf(wA, v[kw + 2], a2);
                    a3 = fmaf(wA, v[kw + 3], a3);
                }
#pragma unroll
                for (int j = 0; j < 10; j++) v[j] = rm[j];
#pragma unroll
                for (int kw = 0; kw < 7; kw++) {
                    float wM = s_w[49 + kh * 7 + kw];
                    a0 = fmaf(wM, v[kw],     a0);
                    a1 = fmaf(wM, v[kw + 1], a1);
                    a2 = fmaf(wM, v[kw + 2], a2);
                    a3 = fmaf(wM, v[kw + 3], a3);
                }
            }
            float4 sg;
            sg.x = 1.0f / (1.0f + __expf(-a0));
            sg.y = 1.0f / (1.0f + __expf(-a1));
            sg.z = 1.0f / (1.0f + __expf(-a2));
            sg.w = 1.0f / (1.0f + __expf(-a3));
            *reinterpret_cast<float4*>(g_s + (size_t)b * HW + (h0 + ty) * 256 + w0 + ow0) = sg;

            __syncthreads();
            if (tid == 0) {
                __threadfence();
                atomicAdd(&conv_done[b], 1);
            }
            __syncthreads();
        }

        // ================= mul(batch p-2) =================
        if (p >= 2) {
            const int b = p - 2;
            gate(conv_done + b, CONV_UNITS);

            const float4* xb = reinterpret_cast<const float4*>(x + (size_t)b * PLANE);
            float4* ob = reinterpret_cast<float4*>(out + (size_t)b * PLANE);
            const float4* sb = reinterpret_cast<const float4*>(g_s + (size_t)b * HW);

            for (int mu = 0; mu < nm; mu++) {
                const int t = (m0 + mu) * 256 + tid;
                const int q4 = t & (HWf4 - 1);

                float4 xv = __ldcs(xb + t);
                float4 sv = __ldcg(sb + q4);
                xv.x *= sv.x; xv.y *= sv.y; xv.z *= sv.z; xv.w *= sv.w;
                __stcs(ob + t, xv);
            }
        }
    }
}

extern "C" void kernel_launch(void* const* d_in, const int* in_sizes, int n_in,
                              void* d_out, int out_size) {
    const float* x  = (const float*)d_in[0];
    const float* cw = (const float*)d_in[1];
    const float* cb = (const float*)d_in[2];
    float* out = (float*)d_out;

    k_reset<<<1, 32>>>();
    k_main<<<NB, 256>>>(x, cw, cb, out);
}

// round 7
// speedup vs baseline: 3.9075x; 1.3581x over previous
#include <cuda_runtime.h>
#include <cuda_bf16.h>

// x: [B=16, C=64, H=256, W=256] fp32; conv_w [1,2,7,7]; conv_b [1]
// out = x * sigmoid(conv7x7(concat(mean_c(x), max_c(x))) + b)
//
// 3-kernel pipeline (launch-boundary deps only):
//  K1 reduce: channel mean+max  (256 MB read, near-ceiling measured 83%)
//  K2 conv:   7x7 + bias + sigmoid on 2-ch map (cheap, register window)
//  K3 mul:    out = x * s, 4 float4/thread with 8 loads batched (MLP=8)

#define B 16
#define C 64
#define HW 65536           // 256*256
#define HWf4 16384         // HW/4
#define PLANE (C * HW)     // 2^22 elements (16 MB)

__device__ float g_att[B * 2 * HW];   // [b][{avg,max}][hw]
__device__ float g_s[B * HW];

// ---------------------------------------------------------------------------
// K1: per-pixel channel mean+max. One thread = one float4-pixel, 64 channels.
// ---------------------------------------------------------------------------
__global__ void k_reduce(const float* __restrict__ x) {
    int t = blockIdx.x * blockDim.x + threadIdx.x;        // [0, B*HWf4)
    int b  = t >> 14;
    int q4 = t & (HWf4 - 1);

    const float4* xb = reinterpret_cast<const float4*>(x + (size_t)b * PLANE);

    float4 v = __ldcs(xb + q4);                            // c = 0
    float sx = v.x, sy = v.y, sz = v.z, sw = v.w;
    float mx = v.x, my = v.y, mz = v.z, mw = v.w;

#pragma unroll 8
    for (int c = 1; c < C; c++) {
        float4 u = __ldcs(xb + (size_t)c * HWf4 + q4);
        sx += u.x; sy += u.y; sz += u.z; sw += u.w;
        mx = fmaxf(mx, u.x); my = fmaxf(my, u.y);
        mz = fmaxf(mz, u.z); mw = fmaxf(mw, u.w);
    }

    const float inv = 1.0f / 64.0f;
    float4* avg_out = reinterpret_cast<float4*>(g_att + (size_t)b * 2 * HW);
    float4* max_out = reinterpret_cast<float4*>(g_att + (size_t)b * 2 * HW + HW);
    avg_out[q4] = make_float4(sx * inv, sy * inv, sz * inv, sw * inv);
    max_out[q4] = make_float4(mx, my, mz, mw);
}

// ---------------------------------------------------------------------------
// K2: 7x7 conv + bias + sigmoid -> g_s. 64x16 tile, register sliding window.
// Grid: (4, 16, B), 256 threads. Thread owns 4 outputs in w.
// ---------------------------------------------------------------------------
__global__ void k_conv(const float* __restrict__ cw, const float* __restrict__ cb) {
    __shared__ float s_avg[22 * 72];
    __shared__ float s_mx[22 * 72];
    __shared__ float s_w[98];
    __shared__ float s_b;

    const int b  = blockIdx.z;
    const int w0 = blockIdx.x * 64;
    const int h0 = blockIdx.y * 16;
    const int tid = threadIdx.x;

    if (tid < 98) s_w[tid] = cw[tid];
    if (tid == 98) s_b = cb[0];

    const float* avgp = g_att + (size_t)b * 2 * HW;
    const float* maxp = avgp + HW;

    for (int i = tid; i < 22 * 70; i += 256) {
        int dy = i / 70, dx = i - dy * 70;
        int hh = h0 - 3 + dy, ww = w0 - 3 + dx;
        float a = 0.f, m = 0.f;
        if (hh >= 0 && hh < 256 && ww >= 0 && ww < 256) {
            int ii = hh * 256 + ww;
            a = avgp[ii];
            m = maxp[ii];
        }
        s_avg[dy * 72 + dx] = a;
        s_mx[dy * 72 + dx]  = m;
    }
    __syncthreads();

    const int tx = tid & 15;
    const int ty = tid >> 4;
    const int ow0 = tx * 4;

    float a0 = s_b, a1 = a0, a2 = a0, a3 = a0;
#pragma unroll
    for (int kh = 0; kh < 7; kh++) {
        const float* ra = s_avg + (ty + kh) * 72 + ow0;
        const float* rm = s_mx  + (ty + kh) * 72 + ow0;
        float v[10];
#pragma unroll
        for (int j = 0; j < 10; j++) v[j] = ra[j];
#pragma unroll
        for (int kw = 0; kw < 7; kw++) {
            float wA = s_w[kh * 7 + kw];
            a0 = fmaf(wA, v[kw],     a0);
            a1 = fmaf(wA, v[kw + 1], a1);
            a2 = fmaf(wA, v[kw + 2], a2);
            a3 = fmaf(wA, v[kw + 3], a3);
        }
#pragma unroll
        for (int j = 0; j < 10; j++) v[j] = rm[j];
#pragma unroll
        for (int kw = 0; kw < 7; kw++) {
            float wM = s_w[49 + kh * 7 + kw];
            a0 = fmaf(wM, v[kw],     a0);
            a1 = fmaf(wM, v[kw + 1], a1);
            a2 = fmaf(wM, v[kw + 2], a2);
            a3 = fmaf(wM, v[kw + 3], a3);
        }
    }
    float4 sg;
    sg.x = 1.0f / (1.0f + __expf(-a0));
    sg.y = 1.0f / (1.0f + __expf(-a1));
    sg.z = 1.0f / (1.0f + __expf(-a2));
    sg.w = 1.0f / (1.0f + __expf(-a3));
    *reinterpret_cast<float4*>(g_s + (size_t)b * HW + (h0 + ty) * 256 + w0 + ow0) = sg;
}

// ---------------------------------------------------------------------------
// K3: out = x * s. One thread = 4 float4s; 8 loads (4 x + 4 s) batched up
// front for MLP=8. Block covers 1024 consecutive f4 (same batch).
// ---------------------------------------------------------------------------
__global__ void k_mul(const float* __restrict__ x, float* __restrict__ out) {
    const int base = blockIdx.x * 1024 + threadIdx.x;      // f4 index of first load
    const int b = base >> 20;                              // PLANE/4 = 2^20 per batch

    const float4* xf = reinterpret_cast<const float4*>(x);
    float4* of = reinterpret_cast<float4*>(out);
    const float4* sb = reinterpret_cast<const float4*>(g_s + (size_t)b * HW);

    float4 xv[4], sv[4];
#pragma unroll
    for (int k = 0; k < 4; k++) xv[k] = __ldcs(xf + base + k * 256);
#pragma unroll
    for (int k = 0; k < 4; k++) {
        int q4 = (base + k * 256) & (HWf4 - 1);
        sv[k] = __ldg(sb + q4);
    }
#pragma unroll
    for (int k = 0; k < 4; k++) {
        xv[k].x *= sv[k].x; xv[k].y *= sv[k].y;
        xv[k].z *= sv[k].z; xv[k].w *= sv[k].w;
        __stcs(of + base + k * 256, xv[k]);
    }
}

// ---------------------------------------------------------------------------
extern "C" void kernel_launch(void* const* d_in, const int* in_sizes, int n_in,
                              void* d_out, int out_size) {
    const float* x  = (const float*)d_in[0];
    const float* cw = (const float*)d_in[1];
    const float* cb = (const float*)d_in[2];
    float* out = (float*)d_out;

    k_reduce<<<(B * HWf4) / 256, 256>>>(x);

    dim3 g2(4, 16, B);
    k_conv<<<g2, 256>>>(cw, cb);

    k_mul<<<(B * (PLANE / 4)) / 1024, 256>>>(x, out);
}